// round 15
// baseline (speedup 1.0000x reference)
#include <cuda_runtime.h>

// Problem constants
#define BB 2
#define HH 160
#define WW 192
#define DD 160
#define NN (HH * WW * DD)
#define WD (WW * DD)             // 30,720

// Tile geometry: 10(h) x 16(w) x 32(z), halo 4
#define TH 10
#define TW 16
#define TZ 32
#define HALO 4
#define FY (TH + 2*HALO)         // 18
#define FX (TW + 2*HALO)         // 24
#define FZ (TZ + 2*HALO)         // 40
#define FOOT (FY * FX * FZ)      // 17,280 floats
#define SMEM_BYTES (FOOT * 4)    // 69,120 B -> 3 blocks/SM @ 512 thr

#define NBH (HH / TH)            // 16
#define NBW (WW / TW)            // 12
#define NBZ (DD / TZ)            // 5
#define NBLK (BB * NBZ * NBH * NBW)   // 1920

#define NTHREADS 512
#define NWARPS (NTHREADS / 32)   // 16  (== TW: one w-column per warp)
#define NITER TH                 // 10 gather iterations per warp
#define NROWS (FY * FX)          // 432 fill rows; 27 per warp exactly
#define ROWS_PER_WARP (NROWS / NWARPS)   // 27

__global__ __launch_bounds__(NTHREADS, 3) void spatial_deformer3d_tiled(
    const float* __restrict__ X,     // interleaved [B,H,W,D,2]
    const float* __restrict__ def,   // [B,H,W,D,3]
    float* __restrict__ out)         // [B,H,W,D,1]
{
    extern __shared__ float sm[];

    int bi = blockIdx.x;
    int tw = bi % NBW;
    int th = (bi / NBW) % NBH;
    int tz = (bi / (NBW * NBH)) % NBZ;
    int b  = bi / (NBW * NBH * NBZ);

    int h0 = th * TH, w0 = tw * TW, zt0 = tz * TZ;
    int fy0 = h0 - HALO, fx0 = w0 - HALO, fz0 = zt0 - HALO;

    const float* __restrict__ Xb = X + (size_t)b * NN * 2;

    int warp = threadIdx.x >> 5;
    int lane = threadIdx.x & 31;

    // ---- Gather index setup: gw constant per warp, t advances by WD/iter ----
    int gw = w0 + warp;                       // NWARPS == TW
    int t  = ((b * HH + h0) * WW + gw) * DD + zt0 + lane;
    const float* dv = def + (size_t)t * 3;
    float xw = (float)gw;
    float zf = (float)(zt0 + lane);
    float yh = (float)h0;

    // Prefetch first iteration's deformation (retires under the fill phase).
    float dx = __ldg(dv + 0);
    float dy = __ldg(dv + 1);
    float dz = __ldg(dv + 2);

    // ---- Fill footprint: warp owns 27 contiguous (ly,lx) rows ----
    // smem layout: ((ly*FX + lx)*FZ + lz). Halo clamped (edge replication).
    {
        // Per-lane chunk: lane k covers z pair (fz0+2k, fz0+2k+1), k < 20.
        bool kact = lane < (FZ / 2);
        int zraw = fz0 + 2 * lane;
        int z0c = min(max(zraw, 0), DD - 1);
        int z1c = min(max(zraw + 1, 0), DD - 1);
        bool pairc = (z1c == z0c + 1);        // true => z0c even & unclamped

        int row0 = warp * ROWS_PER_WARP;
        int ly = row0 / FX;
        int lx = row0 - ly * FX;
        float* dst = sm + row0 * FZ + 2 * lane;

        #pragma unroll 3
        for (int j = 0; j < ROWS_PER_WARP; j++) {
            int gy = min(max(fy0 + ly, 0), HH - 1);
            int gx = min(max(fx0 + lx, 0), WW - 1);
            const float* src = Xb + (gy * WW + gx) * (DD * 2);
            if (kact) {
                float2 v;
                if (pairc) {
                    float4 q = *reinterpret_cast<const float4*>(src + 2 * z0c);
                    v = make_float2(q.x, q.z);
                } else {
                    float s = __ldg(src + 2 * z0c);   // z0c == z1c (replicated)
                    v = make_float2(s, s);
                }
                *reinterpret_cast<float2*>(dst) = v;
            }
            dst += FZ;
            lx++;
            if (lx == FX) { lx = 0; ly++; }
        }
    }
    __syncthreads();

    // Interior fast-path bounds: cell (i,i+1) needs no clamping AND lies in
    // the footprint  <=>  lo <= i <= hi per axis.
    int xlo = max(0, fx0), xhi = min(WW - 2, fx0 + FX - 2);
    int ylo = max(0, fy0), yhi = min(HH - 2, fy0 + FY - 2);
    int zlo = max(0, fz0), zhi = min(DD - 2, fz0 + FZ - 2);

    // ---- Gather: warp = one w-column; gh advances by 1 per iteration ----
    #pragma unroll 1
    for (int i = 0; i < NITER; i++) {
        // Depth-1 rotating prefetch (last iteration re-reads current: in-bounds).
        int tn            = (i < NITER - 1) ? t + WD : t;
        const float* dvn  = (i < NITER - 1) ? dv + 3 * WD : dv;
        float dxn = __ldg(dvn + 0);
        float dyn = __ldg(dvn + 1);
        float dzn = __ldg(dvn + 2);

        float x = xw + dx;
        float y = yh + dy;
        float z = zf + dz;

        int ix = __float2int_rd(x);
        int iy = __float2int_rd(y);
        int iz = __float2int_rd(z);

        float res;

        int ok = (ix - xlo) | (xhi - ix) |
                 (iy - ylo) | (yhi - iy) |
                 (iz - zlo) | (zhi - iz);
        if (ok >= 0) {
            // Tier 1: interior. No clamping possible; x1=x0+1 each axis.
            float wx1 = x - (float)ix;      // exact (Sterbenz)
            float wy1 = y - (float)iy;
            float wz1 = z - (float)iz;
            float wx0 = 1.0f - wx1;         // == x1f - x here, bit-exact
            float wy0 = 1.0f - wy1;
            float wz0 = 1.0f - wz1;

            int base = ((iy - fy0) * FX + (ix - fx0)) * FZ + (iz - fz0);

            float p000 = sm[base];
            float p001 = sm[base + 1];
            float p010 = sm[base + FZ];
            float p011 = sm[base + FZ + 1];
            float p100 = sm[base + FX * FZ];
            float p101 = sm[base + FX * FZ + 1];
            float p110 = sm[base + FX * FZ + FZ];
            float p111 = sm[base + FX * FZ + FZ + 1];

            float v00 = fmaf(wz0, p000, wz1 * p001);
            float v01 = fmaf(wz0, p010, wz1 * p011);
            float v10 = fmaf(wz0, p100, wz1 * p101);
            float v11 = fmaf(wz0, p110, wz1 * p111);
            float v0 = fmaf(wx0, v00, wx1 * v01);
            float v1 = fmaf(wx0, v10, wx1 * v11);
            res = fmaf(wy0, v0, wy1 * v1);
        } else {
            // Reference clamp semantics (weights from CLIPPED coords).
            int x0 = max(0, min(WW - 1, ix));
            int x1 = max(0, min(WW - 1, ix + 1));
            int y0 = max(0, min(HH - 1, iy));
            int y1 = max(0, min(HH - 1, iy + 1));
            int z0 = max(0, min(DD - 1, iz));
            int z1 = max(0, min(DD - 1, iz + 1));

            float wx0 = (float)x1 - x;
            float wx1 = x - (float)x0;
            float wy0 = (float)y1 - y;
            float wy1 = y - (float)y0;
            float wz0 = (float)z1 - z;
            float wz1 = z - (float)z0;

            int lx0 = x0 - fx0, lx1 = x1 - fx0;
            int ly0 = y0 - fy0, ly1 = y1 - fy0;
            int lz0 = z0 - fz0, lz1 = z1 - fz0;

            float p000, p001, p010, p011, p100, p101, p110, p111;

            // Tier 2: clamped cell still inside footprint (smem is
            // edge-replicated, so values match global exactly).
            int ok2 = lx0 | ly0 | lz0 |
                      (FX - 1 - lx1) | (FY - 1 - ly1) | (FZ - 1 - lz1);
            if (ok2 >= 0) {
                int r00 = (ly0 * FX + lx0) * FZ;
                int r01 = (ly0 * FX + lx1) * FZ;
                int r10 = (ly1 * FX + lx0) * FZ;
                int r11 = (ly1 * FX + lx1) * FZ;
                p000 = sm[r00 + lz0];
                p001 = sm[r00 + lz1];
                p010 = sm[r01 + lz0];
                p011 = sm[r01 + lz1];
                p100 = sm[r10 + lz0];
                p101 = sm[r10 + lz1];
                p110 = sm[r11 + lz0];
                p111 = sm[r11 + lz1];
            } else {
                // Tier 3 (P ~ 1e-4): |d| > HALO, exact global fallback.
                int g00 = (y0 * WW + x0) * DD;
                int g01 = (y0 * WW + x1) * DD;
                int g10 = (y1 * WW + x0) * DD;
                int g11 = (y1 * WW + x1) * DD;
                p000 = __ldg(Xb + (g00 + z0) * 2);
                p001 = __ldg(Xb + (g00 + z1) * 2);
                p010 = __ldg(Xb + (g01 + z0) * 2);
                p011 = __ldg(Xb + (g01 + z1) * 2);
                p100 = __ldg(Xb + (g10 + z0) * 2);
                p101 = __ldg(Xb + (g10 + z1) * 2);
                p110 = __ldg(Xb + (g11 + z0) * 2);
                p111 = __ldg(Xb + (g11 + z1) * 2);
            }

            float v00 = fmaf(wz0, p000, wz1 * p001);
            float v01 = fmaf(wz0, p010, wz1 * p011);
            float v10 = fmaf(wz0, p100, wz1 * p101);
            float v11 = fmaf(wz0, p110, wz1 * p111);
            float v0 = fmaf(wx0, v00, wx1 * v01);
            float v1 = fmaf(wx0, v10, wx1 * v11);
            res = fmaf(wy0, v0, wy1 * v1);
        }

        out[t] = res;

        // Rotate pipeline.
        t = tn;
        dv = dvn;
        dx = dxn; dy = dyn; dz = dzn;
        yh += 1.0f;
    }
}

extern "C" void kernel_launch(void* const* d_in, const int* in_sizes, int n_in,
                              void* d_out, int out_size) {
    const float* X   = (const float*)d_in[0];   // [2,160,192,160,2]
    const float* def = (const float*)d_in[1];   // [2,160,192,160,3]
    float* out       = (float*)d_out;

    cudaFuncSetAttribute(spatial_deformer3d_tiled,
                         cudaFuncAttributeMaxDynamicSharedMemorySize, SMEM_BYTES);

    spatial_deformer3d_tiled<<<NBLK, NTHREADS, SMEM_BYTES>>>(X, def, out);
}

// round 16
// speedup vs baseline: 1.3223x; 1.3223x over previous
#include <cuda_runtime.h>

// Problem constants
#define BB 2
#define HH 160
#define WW 192
#define DD 160
#define NN (HH * WW * DD)
#define WD (WW * DD)             // 30,720

// Tile geometry: 10(h) x 16(w) x 32(z), halo 4
#define TH 10
#define TW 16
#define TZ 32
#define HALO 4
#define FY (TH + 2*HALO)         // 18
#define FX (TW + 2*HALO)         // 24
#define FZ (TZ + 2*HALO)         // 40
#define FOOT (FY * FX * FZ)      // 17,280 floats
#define SMEM_BYTES (FOOT * 4)    // 69,120 B -> 3 blocks/SM @ 512 thr

#define NBH (HH / TH)            // 16
#define NBW (WW / TW)            // 12
#define NBZ (DD / TZ)            // 5
#define NBLK (BB * NBZ * NBH * NBW)   // 1920

#define NTHREADS 512
#define NWARPS (NTHREADS / 32)   // 16  (== TW: one w-column per warp)
#define NITER TH                 // 10 gather iterations per warp
#define NROWS (FY * FX)          // 432 fill rows of FZ elems

__global__ __launch_bounds__(NTHREADS, 3) void spatial_deformer3d_tiled(
    const float* __restrict__ X,     // interleaved [B,H,W,D,2]
    const float* __restrict__ def,   // [B,H,W,D,3]
    float* __restrict__ out)         // [B,H,W,D,1]
{
    extern __shared__ float sm[];

    int bi = blockIdx.x;
    int tw = bi % NBW;
    int th = (bi / NBW) % NBH;
    int tz = (bi / (NBW * NBH)) % NBZ;
    int b  = bi / (NBW * NBH * NBZ);

    int h0 = th * TH, w0 = tw * TW, zt0 = tz * TZ;
    int fy0 = h0 - HALO, fx0 = w0 - HALO, fz0 = zt0 - HALO;

    const float* __restrict__ Xb = X + (size_t)b * NN * 2;

    int warp = threadIdx.x >> 5;
    int lane = threadIdx.x & 31;

    // ---- Gather index setup: gw constant per warp (NWARPS == TW),
    //      t advances by WD per iteration ----
    int gw = w0 + warp;
    int t  = ((b * HH + h0) * WW + gw) * DD + zt0 + lane;
    const float* dv = def + (size_t)t * 3;
    float xw = (float)gw;
    float zf = (float)(zt0 + lane);
    float yh = (float)h0;

    // Prefetch first iteration's deformation (retires under the fill phase).
    float dx = __ldg(dv + 0);
    float dy = __ldg(dv + 1);
    float dz = __ldg(dv + 2);

    // ---- Fill footprint: R10 strided pattern (16 warps, 8 outstanding LDGs) ----
    // smem layout: ((ly*FX + lx)*FZ + lz). Halo clamped (edge replication).
    {
        int gzA = min(max(fz0 + lane, 0), DD - 1) * 2;
        int gzB = min(max(fz0 + lane + 32, 0), DD - 1) * 2;   // lanes < FZ-32

        #pragma unroll 4
        for (int row = warp; row < NROWS; row += NWARPS) {
            int ly = row / FX;
            int lx = row - ly * FX;
            int gy = min(max(fy0 + ly, 0), HH - 1);
            int gx = min(max(fx0 + lx, 0), WW - 1);
            const float* src = Xb + (gy * WW + gx) * (DD * 2);
            float* dst = sm + row * FZ;
            dst[lane] = __ldg(src + gzA);
            if (lane < FZ - 32)
                dst[lane + 32] = __ldg(src + gzB);
        }
    }
    __syncthreads();

    // Interior fast-path bounds: cell (i,i+1) needs no clamping AND lies in
    // the footprint  <=>  lo <= i <= hi per axis.
    int xlo = max(0, fx0), xhi = min(WW - 2, fx0 + FX - 2);
    int ylo = max(0, fy0), yhi = min(HH - 2, fy0 + FY - 2);
    int zlo = max(0, fz0), zhi = min(DD - 2, fz0 + FZ - 2);

    // ---- Gather: warp = one w-column; gh advances by 1 per iteration ----
    #pragma unroll 1
    for (int i = 0; i < NITER; i++) {
        // Depth-1 rotating prefetch (last iteration re-reads current: in-bounds).
        int tn           = (i < NITER - 1) ? t + WD : t;
        const float* dvn = (i < NITER - 1) ? dv + 3 * WD : dv;
        float dxn = __ldg(dvn + 0);
        float dyn = __ldg(dvn + 1);
        float dzn = __ldg(dvn + 2);

        float x = xw + dx;
        float y = yh + dy;
        float z = zf + dz;

        int ix = __float2int_rd(x);
        int iy = __float2int_rd(y);
        int iz = __float2int_rd(z);

        float res;

        int ok = (ix - xlo) | (xhi - ix) |
                 (iy - ylo) | (yhi - iy) |
                 (iz - zlo) | (zhi - iz);
        if (ok >= 0) {
            // Tier 1: interior. No clamping possible; x1=x0+1 each axis.
            float wx1 = x - (float)ix;      // exact (Sterbenz)
            float wy1 = y - (float)iy;
            float wz1 = z - (float)iz;
            float wx0 = 1.0f - wx1;         // == x1f - x here, bit-exact
            float wy0 = 1.0f - wy1;
            float wz0 = 1.0f - wz1;

            int base = ((iy - fy0) * FX + (ix - fx0)) * FZ + (iz - fz0);

            float p000 = sm[base];
            float p001 = sm[base + 1];
            float p010 = sm[base + FZ];
            float p011 = sm[base + FZ + 1];
            float p100 = sm[base + FX * FZ];
            float p101 = sm[base + FX * FZ + 1];
            float p110 = sm[base + FX * FZ + FZ];
            float p111 = sm[base + FX * FZ + FZ + 1];

            float v00 = fmaf(wz0, p000, wz1 * p001);
            float v01 = fmaf(wz0, p010, wz1 * p011);
            float v10 = fmaf(wz0, p100, wz1 * p101);
            float v11 = fmaf(wz0, p110, wz1 * p111);
            float v0 = fmaf(wx0, v00, wx1 * v01);
            float v1 = fmaf(wx0, v10, wx1 * v11);
            res = fmaf(wy0, v0, wy1 * v1);
        } else {
            // Reference clamp semantics (weights from CLIPPED coords).
            int x0 = max(0, min(WW - 1, ix));
            int x1 = max(0, min(WW - 1, ix + 1));
            int y0 = max(0, min(HH - 1, iy));
            int y1 = max(0, min(HH - 1, iy + 1));
            int z0 = max(0, min(DD - 1, iz));
            int z1 = max(0, min(DD - 1, iz + 1));

            float wx0 = (float)x1 - x;
            float wx1 = x - (float)x0;
            float wy0 = (float)y1 - y;
            float wy1 = y - (float)y0;
            float wz0 = (float)z1 - z;
            float wz1 = z - (float)z0;

            int lx0 = x0 - fx0, lx1 = x1 - fx0;
            int ly0 = y0 - fy0, ly1 = y1 - fy0;
            int lz0 = z0 - fz0, lz1 = z1 - fz0;

            float p000, p001, p010, p011, p100, p101, p110, p111;

            // Tier 2: clamped cell still inside footprint (smem is
            // edge-replicated, so values match global exactly).
            int ok2 = lx0 | ly0 | lz0 |
                      (FX - 1 - lx1) | (FY - 1 - ly1) | (FZ - 1 - lz1);
            if (ok2 >= 0) {
                int r00 = (ly0 * FX + lx0) * FZ;
                int r01 = (ly0 * FX + lx1) * FZ;
                int r10 = (ly1 * FX + lx0) * FZ;
                int r11 = (ly1 * FX + lx1) * FZ;
                p000 = sm[r00 + lz0];
                p001 = sm[r00 + lz1];
                p010 = sm[r01 + lz0];
                p011 = sm[r01 + lz1];
                p100 = sm[r10 + lz0];
                p101 = sm[r10 + lz1];
                p110 = sm[r11 + lz0];
                p111 = sm[r11 + lz1];
            } else {
                // Tier 3 (P ~ 1e-4): |d| > HALO, exact global fallback.
                int g00 = (y0 * WW + x0) * DD;
                int g01 = (y0 * WW + x1) * DD;
                int g10 = (y1 * WW + x0) * DD;
                int g11 = (y1 * WW + x1) * DD;
                p000 = __ldg(Xb + (g00 + z0) * 2);
                p001 = __ldg(Xb + (g00 + z1) * 2);
                p010 = __ldg(Xb + (g01 + z0) * 2);
                p011 = __ldg(Xb + (g01 + z1) * 2);
                p100 = __ldg(Xb + (g10 + z0) * 2);
                p101 = __ldg(Xb + (g10 + z1) * 2);
                p110 = __ldg(Xb + (g11 + z0) * 2);
                p111 = __ldg(Xb + (g11 + z1) * 2);
            }

            float v00 = fmaf(wz0, p000, wz1 * p001);
            float v01 = fmaf(wz0, p010, wz1 * p011);
            float v10 = fmaf(wz0, p100, wz1 * p101);
            float v11 = fmaf(wz0, p110, wz1 * p111);
            float v0 = fmaf(wx0, v00, wx1 * v01);
            float v1 = fmaf(wx0, v10, wx1 * v11);
            res = fmaf(wy0, v0, wy1 * v1);
        }

        out[t] = res;

        // Rotate pipeline.
        t = tn;
        dv = dvn;
        dx = dxn; dy = dyn; dz = dzn;
        yh += 1.0f;
    }
}

extern "C" void kernel_launch(void* const* d_in, const int* in_sizes, int n_in,
                              void* d_out, int out_size) {
    const float* X   = (const float*)d_in[0];   // [2,160,192,160,2]
    const float* def = (const float*)d_in[1];   // [2,160,192,160,3]
    float* out       = (float*)d_out;

    cudaFuncSetAttribute(spatial_deformer3d_tiled,
                         cudaFuncAttributeMaxDynamicSharedMemorySize, SMEM_BYTES);

    spatial_deformer3d_tiled<<<NBLK, NTHREADS, SMEM_BYTES>>>(X, def, out);
}